// round 16
// baseline (speedup 1.0000x reference)
#include <cuda_runtime.h>
#include <cuda_bf16.h>
#include <cstdint>

typedef unsigned long long u64;

// ---------------- problem constants (fixed by setup_inputs) ----------------
#define S_TOK 3120          // F*H*W = 2*30*52
#define DIM_  1536
#define NH    12
#define HD    128
#define KV    5632          // attention window length (== MAX_ATTN exactly)
#define NKT   88            // KV / 64
#define NEW0  2512          // offset of new tokens inside window (7800-5288)
#define WIN0  5288          // window start in cache
#define SD    (S_TOK*DIM_)              // 4,792,320
#define KVD   ((size_t)NH*KV*HD)        // 8,650,752
#define WSZ   (DIM_*DIM_)               // 2,359,296
#define QSCALE 0.08838834764831845f     // 1/sqrt(128)

// fp32 scratch: yq | yk | yv
__device__ float g_scratch[3*(size_t)SD];
// split-bf16 scratch (GEMM operands)
__device__ __align__(16) __nv_bfloat16 g_xhi[SD], g_xlo[SD];
__device__ __align__(16) __nv_bfloat16 g_whi[4*(size_t)WSZ], g_wlo[4*(size_t)WSZ];
__device__ __align__(16) __nv_bfloat16 g_ohi[SD], g_olo[SD];
// split-bf16 attention operands (head-major)
__device__ __align__(16) __nv_bfloat16 g_qh[SD], g_ql[SD];
__device__ __align__(16) __nv_bfloat16 g_kh[KVD], g_kl[KVD];
__device__ __align__(16) __nv_bfloat16 g_vh[KVD], g_vl[KVD];

// ---------------- mma.sync / ldmatrix / cp.async helpers (NOT a-gated) ------
__device__ __forceinline__ uint32_t smem_u32(const void* p) {
    uint32_t a; asm("{ .reg .u64 t; cvta.to.shared.u64 t, %1; cvt.u32.u64 %0, t; }" : "=r"(a) : "l"(p));
    return a;
}
__device__ __forceinline__ void ldsm4(uint32_t* r, uint32_t a) {
    asm volatile("ldmatrix.sync.aligned.m8n8.x4.shared.b16 {%0,%1,%2,%3}, [%4];"
                 : "=r"(r[0]), "=r"(r[1]), "=r"(r[2]), "=r"(r[3]) : "r"(a));
}
__device__ __forceinline__ void ldsm4t(uint32_t* r, uint32_t a) {
    asm volatile("ldmatrix.sync.aligned.m8n8.x4.trans.shared.b16 {%0,%1,%2,%3}, [%4];"
                 : "=r"(r[0]), "=r"(r[1]), "=r"(r[2]), "=r"(r[3]) : "r"(a));
}
__device__ __forceinline__ void mma16816(float* c, const uint32_t* a, uint32_t b0, uint32_t b1) {
    asm volatile("mma.sync.aligned.m16n8k16.row.col.f32.bf16.bf16.f32 "
                 "{%0,%1,%2,%3}, {%4,%5,%6,%7}, {%8,%9}, {%0,%1,%2,%3};"
                 : "+f"(c[0]), "+f"(c[1]), "+f"(c[2]), "+f"(c[3])
                 : "r"(a[0]), "r"(a[1]), "r"(a[2]), "r"(a[3]), "r"(b0), "r"(b1));
}
__device__ __forceinline__ void cp16(uint32_t d, const void* s) {
    asm volatile("cp.async.cg.shared.global [%0], [%1], 16;" :: "r"(d), "l"(s));
}
__device__ __forceinline__ void cp16z(uint32_t d, const void* s, int sz) {
    asm volatile("cp.async.cg.shared.global [%0], [%1], 16, %2;" :: "r"(d), "l"(s), "r"(sz));
}
__device__ __forceinline__ void cp_commit() {
    asm volatile("cp.async.commit_group;" ::: "memory");
}
template<int N> __device__ __forceinline__ void cp_wait() {
    asm volatile("cp.async.wait_group %0;" :: "n"(N) : "memory");
}
__device__ __forceinline__ uint32_t sw128(uint32_t off) { return off ^ ((off >> 3) & 0x70); }

// pack two fp32 into bf16x2 hi + residual lo
__device__ __forceinline__ void packsplit(float x, float y, uint32_t& hi, uint32_t& lo) {
    uint32_t h; asm("cvt.rn.bf16x2.f32 %0, %1, %2;" : "=r"(h) : "f"(y), "f"(x));
    float hx = __uint_as_float(h << 16);
    float hy = __uint_as_float(h & 0xffff0000u);
    uint32_t l; asm("cvt.rn.bf16x2.f32 %0, %1, %2;" : "=r"(l) : "f"(y - hy), "f"(x - hx));
    hi = h; lo = l;
}

// ============================================================================
// split fp32 -> (hi, lo) bf16 pair. n4 = elems/4.
// ============================================================================
__global__ void __launch_bounds__(256) split_kernel(
    const float* __restrict__ src, __nv_bfloat16* __restrict__ hi,
    __nv_bfloat16* __restrict__ lo, int n4)
{
    int i = blockIdx.x * 256 + threadIdx.x;
    if (i >= n4) return;
    float4 v = ((const float4*)src)[i];
    uint32_t h0, l0, h1, l1;
    packsplit(v.x, v.y, h0, l0);
    packsplit(v.z, v.w, h1, l1);
    ((uint2*)hi)[i] = make_uint2(h0, h1);
    ((uint2*)lo)[i] = make_uint2(l0, l1);
}

// ============================================================================
// Split-bf16 GEMM (NT) via mma.sync.m16n8k16 — 4-stage cp.async pipeline.
// K-chunk 32. Combined rows: bytes [0,64) = hi cols, [64,128) = lo cols.
// Stage: A[128x128B] @0 (16KB) | W[128x128B] @16KB  -> 32KB; 4 stages = 128KB.
// ============================================================================
#define GST 32768
#define GEMM_SMEM (4*GST)
#define NCH 48

__device__ __forceinline__ void gemm_body(
    const __nv_bfloat16* __restrict__ Ah, const __nv_bfloat16* __restrict__ Al,
    const __nv_bfloat16* __restrict__ Wh, const __nv_bfloat16* __restrict__ Wl,
    const float* __restrict__ bias, float* __restrict__ C, int M,
    int m0, int n0, char* smem)
{
    const uint32_t sb = smem_u32(smem);
    const int tid  = threadIdx.x;
    const int lane = tid & 31;
    const int warp = tid >> 5;
    const int wm = (warp >> 2) * 64;
    const int wn = (warp & 3) * 32;

    float acc[4][4][4];
#pragma unroll
    for (int mi = 0; mi < 4; ++mi)
#pragma unroll
        for (int ni = 0; ni < 4; ++ni)
#pragma unroll
            for (int j = 0; j < 4; ++j) acc[mi][ni][j] = 0.f;

    auto load_stage = [&](int c) {
        const uint32_t db = sb + (c & 3) * GST;
        const int kc = c * 32;
#pragma unroll
        for (int i = 0; i < 8; ++i) {
            const int slot = tid + i * 256;       // 0..2047
            const int tile = slot >> 10;          // 0 = A, 1 = W
            const int row  = (slot >> 3) & 127;
            const int ch   = slot & 7;            // 16B chunk in 128B row
            const int ecol = kc + (ch & 3) * 8;   // bf16 element col
            const uint32_t d = db + tile * 16384 + sw128((uint32_t)(row * 128 + ch * 16));
            if (tile == 0) {
                const int gr = m0 + row;
                const int sz = (gr < M) ? 16 : 0;
                const int gs = (gr < M) ? gr : 0;
                const __nv_bfloat16* base = (ch < 4) ? Ah : Al;
                cp16z(d, base + (size_t)gs * DIM_ + ecol, sz);
            } else {
                const int gr = n0 + row;
                const __nv_bfloat16* base = (ch < 4) ? Wh : Wl;
                cp16(d, base + (size_t)gr * DIM_ + ecol);
            }
        }
    };

    load_stage(0); cp_commit();
    load_stage(1); cp_commit();
    load_stage(2); cp_commit();

    for (int c = 0; c < NCH; ++c) {
        if (c <= NCH - 3) cp_wait<2>();
        else if (c == NCH - 2) cp_wait<1>();
        else cp_wait<0>();
        __syncthreads();
        if (c + 3 < NCH) { load_stage(c + 3); cp_commit(); }

        const uint32_t base = sb + (c & 3) * GST;
        const int rA = wm + (lane & 15);
        const int rW = wn + (lane & 15);
#pragma unroll
        for (int ks = 0; ks < 2; ++ks) {
            const int kb = ks * 32 + ((lane >> 4) << 4);   // byte col in hi half
            uint32_t ah[4][4], al[4][4], wh[2][4], wl[2][4];
#pragma unroll
            for (int mi = 0; mi < 4; ++mi) {
                ldsm4(ah[mi], base + sw128((uint32_t)((rA + mi * 16) * 128 + kb)));
                ldsm4(al[mi], base + sw128((uint32_t)((rA + mi * 16) * 128 + kb + 64)));
            }
#pragma unroll
            for (int nj = 0; nj < 2; ++nj) {
                ldsm4(wh[nj], base + 16384 + sw128((uint32_t)((rW + nj * 16) * 128 + kb)));
                ldsm4(wl[nj], base + 16384 + sw128((uint32_t)((rW + nj * 16) * 128 + kb + 64)));
            }
#pragma unroll
            for (int mi = 0; mi < 4; ++mi)
#pragma unroll
                for (int ni = 0; ni < 4; ++ni) {
                    const int nj = ni >> 1, hf = ni & 1;
                    const uint32_t b0h = wh[nj][hf], b1h = wh[nj][hf + 2];
                    const uint32_t b0l = wl[nj][hf], b1l = wl[nj][hf + 2];
                    mma16816(acc[mi][ni], ah[mi], b0h, b1h);
                    mma16816(acc[mi][ni], al[mi], b0h, b1h);
                    mma16816(acc[mi][ni], ah[mi], b0l, b1l);
                }
        }
    }

    float2 bv[4];
#pragma unroll
    for (int ni = 0; ni < 4; ++ni) {
        const int n = n0 + wn + ni * 8 + (lane & 3) * 2;
        bv[ni] = *(const float2*)&bias[n];
    }
#pragma unroll
    for (int mi = 0; mi < 4; ++mi) {
        const int m = m0 + wm + mi * 16 + (lane >> 2);
#pragma unroll
        for (int ni = 0; ni < 4; ++ni) {
            const int n = n0 + wn + ni * 8 + (lane & 3) * 2;
            if (m < M) {
                float2 o = make_float2(acc[mi][ni][0] + bv[ni].x, acc[mi][ni][1] + bv[ni].y);
                *(float2*)&C[(size_t)m * DIM_ + n] = o;
            }
            if (m + 8 < M) {
                float2 o = make_float2(acc[mi][ni][2] + bv[ni].x, acc[mi][ni][3] + bv[ni].y);
                *(float2*)&C[(size_t)(m + 8) * DIM_ + n] = o;
            }
        }
    }
}

// plain GEMM (output projection)
__global__ void __launch_bounds__(256) gemm_mma(
    const __nv_bfloat16* __restrict__ Ah, const __nv_bfloat16* __restrict__ Al,
    const __nv_bfloat16* __restrict__ Wh, const __nv_bfloat16* __restrict__ Wl,
    const float* __restrict__ bias, float* __restrict__ C, int M)
{
    extern __shared__ __align__(16) char smem[];
    gemm_body(Ah, Al, Wh, Wl, bias, C, M, blockIdx.y * 128, blockIdx.x * 128, smem);
}

// fused QKV GEMM: blockIdx.x in [0,36): which = bx/12, n0 = (bx%12)*128
__global__ void __launch_bounds__(256) gemm_qkv(
    const __nv_bfloat16* __restrict__ Ah, const __nv_bfloat16* __restrict__ Al,
    const __nv_bfloat16* __restrict__ Whb, const __nv_bfloat16* __restrict__ Wlb,
    const float* __restrict__ bq, const float* __restrict__ bk, const float* __restrict__ bv_,
    float* __restrict__ outbase, int M)
{
    extern __shared__ __align__(16) char smem[];
    const int which = blockIdx.x / 12;
    const int n0 = (blockIdx.x % 12) * 128;
    const __nv_bfloat16* Wh = Whb + (size_t)which * WSZ;
    const __nv_bfloat16* Wl = Wlb + (size_t)which * WSZ;
    const float* bias = (which == 0) ? bq : ((which == 1) ? bk : bv_);
    float* C = outbase + (size_t)which * SD;
    gemm_body(Ah, Al, Wh, Wl, bias, C, M, blockIdx.y * 128, n0, smem);
}

// ============================================================================
// Cache window copy -> split bf16 head-major K/V  (tokens [0, NEW0))
// ============================================================================
__global__ void cache_copy_kernel(const float* __restrict__ ck, const float* __restrict__ cv,
                                  __nv_bfloat16* __restrict__ Kh, __nv_bfloat16* __restrict__ Kl,
                                  __nv_bfloat16* __restrict__ Vh, __nv_bfloat16* __restrict__ Vl)
{
    int t = blockIdx.x;                 // 0..2511
    int e = threadIdx.x << 2;           // 384 threads * 4 = 1536
    int n = e >> 7, d = e & 127;
    size_t dst = ((size_t)n * KV + t) * HD + d;
    float4 kv = *(const float4*)&ck[(size_t)(WIN0 + t) * DIM_ + e];
    float4 vv = *(const float4*)&cv[(size_t)(WIN0 + t) * DIM_ + e];
    uint32_t h0, l0, h1, l1;
    packsplit(kv.x, kv.y, h0, l0); packsplit(kv.z, kv.w, h1, l1);
    *(uint2*)&Kh[dst] = make_uint2(h0, h1);
    *(uint2*)&Kl[dst] = make_uint2(l0, l1);
    packsplit(vv.x, vv.y, h0, l0); packsplit(vv.z, vv.w, h1, l1);
    *(uint2*)&Vh[dst] = make_uint2(h0, h1);
    *(uint2*)&Vl[dst] = make_uint2(l0, l1);
}

// ============================================================================
// RMSNorm(1536) + RoPE -> split-bf16 head-major Q, K(@NEW0), V(@NEW0)
// ============================================================================
__global__ void __launch_bounds__(256) norm_rope_kernel(
    const float* __restrict__ yq, const float* __restrict__ yk, const float* __restrict__ yv,
    const float* __restrict__ theta, const float* __restrict__ gq, const float* __restrict__ gk,
    __nv_bfloat16* __restrict__ Qh, __nv_bfloat16* __restrict__ Ql,
    __nv_bfloat16* __restrict__ Kh, __nv_bfloat16* __restrict__ Kl,
    __nv_bfloat16* __restrict__ Vh, __nv_bfloat16* __restrict__ Vl)
{
    const int s = blockIdx.x;
    const int tid = threadIdx.x;
    __shared__ float cs[64], sn[64];
    __shared__ float redq[8], redk[8];

    const int f   = s / 1560;           // frame_seqlen = 30*52
    const int rem = s % 1560;
    const int h   = rem / 52;
    const int w   = rem % 52;

    if (tid < 64) {
        int j = tid;
        int row = (j < 22) ? (5 + f) : ((j < 43) ? h : w);
        float ang = theta[row * 64 + j];
        float sv, cv; sincosf(ang, &sv, &cv);
        cs[j] = cv; sn[j] = sv;
    }

    const float* q = yq + (size_t)s * DIM_;
    const float* k = yk + (size_t)s * DIM_;
    const float* v = yv + (size_t)s * DIM_;

    float sq = 0.f, sk = 0.f;
    for (int e = tid; e < DIM_; e += 256) {
        float a = q[e]; sq += a * a;
        float b = k[e]; sk += b * b;
    }
#pragma unroll
    for (int off = 16; off; off >>= 1) {
        sq += __shfl_xor_sync(0xffffffffu, sq, off);
        sk += __shfl_xor_sync(0xffffffffu, sk, off);
    }
    if ((tid & 31) == 0) { redq[tid >> 5] = sq; redk[tid >> 5] = sk; }
    __syncthreads();
    float tq = 0.f, tk = 0.f;
#pragma unroll
    for (int i = 0; i < 8; ++i) { tq += redq[i]; tk += redk[i]; }
    const float rq = rsqrtf(tq * (1.f / 1536.f) + 1e-6f);
    const float rk = rsqrtf(tk * (1.f / 1536.f) + 1e-6f);

    for (int p = tid; p < 768; p += 256) {
        int n = p >> 6, j = p & 63;
        float c = cs[j], si = sn[j];
        int e = p << 1;
        float xr = q[e]     * rq * gq[e];
        float xi = q[e + 1] * rq * gq[e + 1];
        float qr = (xr * c - xi * si) * QSCALE;
        float qi = (xr * si + xi * c) * QSCALE;
        size_t qo = ((size_t)n * S_TOK + s) * HD + (j << 1);
        uint32_t hi, lo;
        packsplit(qr, qi, hi, lo);
        *(uint32_t*)&Qh[qo] = hi; *(uint32_t*)&Ql[qo] = lo;
        float kr0 = k[e]     * rk * gk[e];
        float ki0 = k[e + 1] * rk * gk[e + 1];
        float kr = kr0 * c - ki0 * si;
        float ki = kr0 * si + ki0 * c;
        size_t ko = ((size_t)n * KV + NEW0 + s) * HD + (j << 1);
        packsplit(kr, ki, hi, lo);
        *(uint32_t*)&Kh[ko] = hi; *(uint32_t*)&Kl[ko] = lo;
        float v0 = v[e], v1 = v[e + 1];
        packsplit(v0, v1, hi, lo);
        *(uint32_t*)&Vh[ko] = hi; *(uint32_t*)&Vl[ko] = lo;
    }
}

// ============================================================================
// Flash attention via mma.sync split-bf16 (full KV, R12 config).
// Block: 128 queries x 1 head, 256 threads. Epilogue writes split-bf16.
// ============================================================================
#define AT_SMEM (2*65536)

__global__ void __launch_bounds__(256, 1) attn_mma(
    const __nv_bfloat16* __restrict__ Qh_, const __nv_bfloat16* __restrict__ Ql_,
    const __nv_bfloat16* __restrict__ Kh_, const __nv_bfloat16* __restrict__ Kl_,
    const __nv_bfloat16* __restrict__ Vh_, const __nv_bfloat16* __restrict__ Vl_,
    __nv_bfloat16* __restrict__ Ohi, __nv_bfloat16* __restrict__ Olo)
{
    extern __shared__ __align__(16) char smem[];
    const uint32_t sb = smem_u32(smem);
    const int tid = threadIdx.x, lane = tid & 31, warp = tid >> 5;
    const int head = blockIdx.y;
    const int q0 = blockIdx.x * 128;

    // ---- stage Q tile (hi at 0, lo at +32768), then load A-fragments ----
#pragma unroll
    for (int i = 0; i < 8; ++i) {
        int slot = tid + i * 256;
        int row = slot >> 4, ch = slot & 15;
        int qg = q0 + row;
        int sz = (qg < S_TOK) ? 16 : 0;
        if (qg >= S_TOK) qg = S_TOK - 1;
        const size_t off = ((size_t)head * S_TOK + qg) * HD + ch * 8;
        uint32_t d = sb + (row << 8) + (((uint32_t)(ch ^ (row & 7))) << 4);
        cp16z(d, Qh_ + off, sz);
        cp16z(d + 32768, Ql_ + off, sz);
    }
    cp_commit(); cp_wait<0>(); __syncthreads();

    uint32_t qh[8][4], ql[8][4];
    {
        const int row = warp * 16 + (lane & 15);
#pragma unroll
        for (int kc = 0; kc < 8; ++kc) {
            int ch = 2 * kc + ((lane >> 4) & 1);
            uint32_t a = sb + (row << 8) + (((uint32_t)(ch ^ (row & 7))) << 4);
            ldsm4(qh[kc], a);
            ldsm4(ql[kc], a + 32768);
        }
    }
    __syncthreads();

    float oacc[16][4];
#pragma unroll
    for (int i = 0; i < 16; ++i)
#pragma unroll
        for (int j = 0; j < 4; ++j) oacc[i][j] = 0.f;
    float mr0 = -1e30f, mr1 = -1e30f, lr0 = 0.f, lr1 = 0.f;

    auto load_kv = [&](int kt, int buf) {
        const uint32_t db = sb + buf * 65536;
        const int t0 = kt * 64;
#pragma unroll
        for (int i = 0; i < 4; ++i) {
            int slot = tid + i * 256;
            int row = slot >> 4, ch = slot & 15;
            const size_t off = ((size_t)head * KV + t0 + row) * HD + ch * 8;
            uint32_t d = (uint32_t)((row << 8) + ((ch ^ (row & 7)) << 4));
            cp16(db + d,         Kh_ + off);
            cp16(db + 16384 + d, Kl_ + off);
            cp16(db + 32768 + d, Vh_ + off);
            cp16(db + 49152 + d, Vl_ + off);
        }
    };

    load_kv(0, 0); cp_commit();

    for (int kt = 0; kt < NKT; ++kt) {
        if (kt < NKT - 1) { load_kv(kt + 1, (kt + 1) & 1); cp_commit(); cp_wait<1>(); }
        else cp_wait<0>();
        __syncthreads();
        const uint32_t kb = sb + (kt & 1) * 65536;

        // ---- S = Q K^T ----
        float sacc[8][4];
#pragma unroll
        for (int i = 0; i < 8; ++i)
#pragma unroll
            for (int j = 0; j < 4; ++j) sacc[i][j] = 0.f;

#pragma unroll
        for (int kc = 0; kc < 8; ++kc) {
#pragma unroll
            for (int ng = 0; ng < 4; ++ng) {
                const int key = 16 * ng + (lane & 15);
                const int ch = 2 * kc + ((lane >> 4) & 1);
                uint32_t a = kb + (key << 8) + (((uint32_t)(ch ^ (key & 7))) << 4);
                uint32_t khf[4], klf[4];
                ldsm4(khf, a);
                ldsm4(klf, a + 16384);
                mma16816(sacc[2 * ng],     qh[kc], khf[0], khf[2]);
                mma16816(sacc[2 * ng],     ql[kc], khf[0], khf[2]);
                mma16816(sacc[2 * ng],     qh[kc], klf[0], klf[2]);
                mma16816(sacc[2 * ng + 1], qh[kc], khf[1], khf[3]);
                mma16816(sacc[2 * ng + 1], ql[kc], khf[1], khf[3]);
                mma16816(sacc[2 * ng + 1], qh[kc], klf[1], klf[3]);
            }
        }

        // ---- online softmax in fragments ----
        float tm0 = -1e30f, tm1 = -1e30f;
#pragma unroll
        for (int i = 0; i < 8; ++i) {
            tm0 = fmaxf(tm0, fmaxf(sacc[i][0], sacc[i][1]));
            tm1 = fmaxf(tm1, fmaxf(sacc[i][2], sacc[i][3]));
        }
        tm0 = fmaxf(tm0, __shfl_xor_sync(0xffffffffu, tm0, 1));
        tm0 = fmaxf(tm0, __shfl_xor_sync(0xffffffffu, tm0, 2));
        tm1 = fmaxf(tm1, __shfl_xor_sync(0xffffffffu, tm1, 1));
        tm1 = fmaxf(tm1, __shfl_xor_sync(0xffffffffu, tm1, 2));
        const float mn0 = fmaxf(mr0, tm0), mn1 = fmaxf(mr1, tm1);
        const float al0 = __expf(mr0 - mn0), al1 = __expf(mr1 - mn1);
        mr0 = mn0; mr1 = mn1;

        float rs0 = 0.f, rs1 = 0.f;
#pragma unroll
        for (int i = 0; i < 8; ++i) {
            sacc[i][0] = __expf(sacc[i][0] - mn0); rs0 += sacc[i][0];
            sacc[i][1] = __expf(sacc[i][1] - mn0); rs0 += sacc[i][1];
            sacc[i][2] = __expf(sacc[i][2] - mn1); rs1 += sacc[i][2];
            sacc[i][3] = __expf(sacc[i][3] - mn1); rs1 += sacc[i][3];
        }
        rs0 += __shfl_xor_sync(0xffffffffu, rs0, 1);
        rs0 += __shfl_xor_sync(0xffffffffu, rs0, 2);
        rs1 += __shfl_xor_sync(0xffffffffu, rs1, 1);
        rs1 += __shfl_xor_sync(0xffffffffu, rs1, 2);
        lr0 = lr0 * al0 + rs0;
        lr1 = lr1 * al1 + rs1;

#pragma unroll
        for (int i = 0; i < 16; ++i) {
            oacc[i][0] *= al0; oacc[i][1] *= al0;
            oacc[i][2] *= al1; oacc[i][3] *= al1;
        }

        // ---- pack P into split-bf16 A-fragments ----
        uint32_t ph[4][4], pl[4][4];
#pragma unroll
        for (int kc = 0; kc < 4; ++kc) {
            packsplit(sacc[2 * kc][0],     sacc[2 * kc][1],     ph[kc][0], pl[kc][0]);
            packsplit(sacc[2 * kc][2],     sacc[2 * kc][3],     ph[kc][1], pl[kc][1]);
            packsplit(sacc[2 * kc + 1][0], sacc[2 * kc + 1][1], ph[kc][2], pl[kc][2]);
            packsplit(sacc[2 * kc + 1][2], sacc[2 * kc + 1][3], ph[kc][3], pl[kc][3]);
        }

        // ---- O += P V ----
#pragma unroll
        for (int kc = 0; kc < 4; ++kc) {
#pragma unroll
            for (int ng = 0; ng < 8; ++ng) {
                const int key = 16 * kc + (lane & 15);
                const int ch = 2 * ng + ((lane >> 4) & 1);
                uint32_t a = kb + 32768 + (key << 8) + (((uint32_t)(ch ^ (key & 7))) << 4);
                uint32_t vhf[4], vlf[4];
                ldsm4t(vhf, a);
                ldsm4t(vlf, a + 16384);
                mma16816(oacc[2 * ng],     ph[kc], vhf[0], vhf[1]);
                mma16816(oacc[2 * ng],     pl[kc], vhf[0], vhf[1]);
                mma16816(oacc[2 * ng],     ph[kc], vlf[0], vlf[1]);
                mma16816(oacc[2 * ng + 1], ph[kc], vhf[2], vhf[3]);
                mma16816(oacc[2 * ng + 1], pl[kc], vhf[2], vhf[3]);
                mma16816(oacc[2 * ng + 1], ph[kc], vlf[2], vlf[3]);
            }
        }
        __syncthreads();
    }

    // ---- epilogue: normalize and write split-bf16 token-major ----
    const float inv0 = 1.f / lr0, inv1 = 1.f / lr1;
    const int r0 = warp * 16 + (lane >> 2);
    const int cn = (lane & 3) * 2;
    const int qa = q0 + r0, qb = qa + 8;
#pragma unroll
    for (int ni = 0; ni < 16; ++ni) {
        const int col = head * HD + ni * 8 + cn;
        uint32_t hi, lo;
        if (qa < S_TOK) {
            packsplit(oacc[ni][0] * inv0, oacc[ni][1] * inv0, hi, lo);
            size_t off = (size_t)qa * DIM_ + col;
            *(uint32_t*)&Ohi[off] = hi; *(uint32_t*)&Olo[off] = lo;
        }
        if (qb < S_TOK) {
            packsplit(oacc[ni][2] * inv1, oacc[ni][3] * inv1, hi, lo);
            size_t off = (size_t)qb * DIM_ + col;
            *(uint32_t*)&Ohi[off] = hi; *(uint32_t*)&Olo[off] = lo;
        }
    }
}

// ============================================================================
extern "C" void kernel_launch(void* const* d_in, const int* in_sizes, int n_in,
                              void* d_out, int out_size)
{
    const float* x     = (const float*)d_in[0];
    const float* theta = (const float*)d_in[1];
    const float* ck    = (const float*)d_in[2];
    const float* cv    = (const float*)d_in[3];
    const float* wq    = (const float*)d_in[4];
    const float* bq    = (const float*)d_in[5];
    const float* wk    = (const float*)d_in[6];
    const float* bk    = (const float*)d_in[7];
    const float* wv    = (const float*)d_in[8];
    const float* bv    = (const float*)d_in[9];
    const float* wo    = (const float*)d_in[10];
    const float* bo    = (const float*)d_in[11];
    const float* gq    = (const float*)d_in[12];
    const float* gk    = (const float*)d_in[13];
    float* out = (float*)d_out;

    float* scr = nullptr;
    cudaGetSymbolAddress((void**)&scr, g_scratch);
    float* yq  = scr;
    float* yk  = scr + (size_t)SD;
    float* yv  = scr + 2 * (size_t)SD;

    __nv_bfloat16 *xhi, *xlo, *whi, *wlo, *ohi, *olo;
    __nv_bfloat16 *Qh, *Ql, *Kh, *Kl, *Vh, *Vl;
    cudaGetSymbolAddress((void**)&xhi, g_xhi);
    cudaGetSymbolAddress((void**)&xlo, g_xlo);
    cudaGetSymbolAddress((void**)&whi, g_whi);
    cudaGetSymbolAddress((void**)&wlo, g_wlo);
    cudaGetSymbolAddress((void**)&ohi, g_ohi);
    cudaGetSymbolAddress((void**)&olo, g_olo);
    cudaGetSymbolAddress((void**)&Qh, g_qh);
    cudaGetSymbolAddress((void**)&Ql, g_ql);
    cudaGetSymbolAddress((void**)&Kh, g_kh);
    cudaGetSymbolAddress((void**)&Kl, g_kl);
    cudaGetSymbolAddress((void**)&Vh, g_vh);
    cudaGetSymbolAddress((void**)&Vl, g_vl);

    cudaFuncSetAttribute(gemm_mma, cudaFuncAttributeMaxDynamicSharedMemorySize, GEMM_SMEM);
    cudaFuncSetAttribute(gemm_qkv, cudaFuncAttributeMaxDynamicSharedMemorySize, GEMM_SMEM);
    cudaFuncSetAttribute(attn_mma, cudaFuncAttributeMaxDynamicSharedMemorySize, AT_SMEM);

    const int SD4 = SD / 4, W4 = WSZ / 4;
    split_kernel<<<(SD4 + 255) / 256, 256>>>(x,  xhi, xlo, SD4);
    split_kernel<<<(W4 + 255) / 256, 256>>>(wq, whi + 0 * (size_t)WSZ, wlo + 0 * (size_t)WSZ, W4);
    split_kernel<<<(W4 + 255) / 256, 256>>>(wk, whi + 1 * (size_t)WSZ, wlo + 1 * (size_t)WSZ, W4);
    split_kernel<<<(W4 + 255) / 256, 256>>>(wv, whi + 2 * (size_t)WSZ, wlo + 2 * (size_t)WSZ, W4);
    split_kernel<<<(W4 + 255) / 256, 256>>>(wo, whi + 3 * (size_t)WSZ, wlo + 3 * (size_t)WSZ, W4);

    // fused QKV projection: grid (36, 25)
    gemm_qkv<<<dim3(36, 25), 256, GEMM_SMEM>>>(xhi, xlo, whi, wlo, bq, bk, bv, scr, S_TOK);

    cache_copy_kernel<<<NEW0, 384>>>(ck, cv, Kh, Kl, Vh, Vl);
    norm_rope_kernel<<<S_TOK, 256>>>(yq, yk, yv, theta, gq, gk, Qh, Ql, Kh, Kl, Vh, Vl);

    // full-KV attention, writes split-bf16 output directly
    attn_mma<<<dim3(25, NH), 256, AT_SMEM>>>(Qh, Ql, Kh, Kl, Vh, Vl, ohi, olo);

    gemm_mma<<<dim3(12, 25), 256, GEMM_SMEM>>>(ohi, olo, whi + 3 * (size_t)WSZ, wlo + 3 * (size_t)WSZ, bo, out, S_TOK);
}

// round 17
// speedup vs baseline: 1.0488x; 1.0488x over previous
#include <cuda_runtime.h>
#include <cuda_bf16.h>
#include <cstdint>

typedef unsigned long long u64;

// ---------------- problem constants (fixed by setup_inputs) ----------------
#define S_TOK 3120          // F*H*W = 2*30*52
#define DIM_  1536
#define NH    12
#define HD    128
#define KV    5632          // attention window length (== MAX_ATTN exactly)
#define NKT   88            // KV / 64
#define NEW0  2512          // offset of new tokens inside window (7800-5288)
#define WIN0  5288          // window start in cache
#define SD    (S_TOK*DIM_)              // 4,792,320
#define KVD   ((size_t)NH*KV*HD)        // 8,650,752
#define WSZ   (DIM_*DIM_)               // 2,359,296
#define QSCALE 0.08838834764831845f     // 1/sqrt(128)

// fp32 scratch: yq | yk | yv
__device__ float g_scratch[3*(size_t)SD];
// split-bf16 scratch (GEMM operands)
__device__ __align__(16) __nv_bfloat16 g_xhi[SD], g_xlo[SD];
__device__ __align__(16) __nv_bfloat16 g_whi[4*(size_t)WSZ], g_wlo[4*(size_t)WSZ];
__device__ __align__(16) __nv_bfloat16 g_ohi[SD], g_olo[SD];
// split-bf16 attention operands (head-major)
__device__ __align__(16) __nv_bfloat16 g_qh[SD], g_ql[SD];
__device__ __align__(16) __nv_bfloat16 g_kh[KVD], g_kl[KVD];
__device__ __align__(16) __nv_bfloat16 g_vh[KVD], g_vl[KVD];

// ---------------- mma.sync / ldmatrix / cp.async helpers (NOT a-gated) ------
__device__ __forceinline__ uint32_t smem_u32(const void* p) {
    uint32_t a; asm("{ .reg .u64 t; cvta.to.shared.u64 t, %1; cvt.u32.u64 %0, t; }" : "=r"(a) : "l"(p));
    return a;
}
__device__ __forceinline__ void ldsm4(uint32_t* r, uint32_t a) {
    asm volatile("ldmatrix.sync.aligned.m8n8.x4.shared.b16 {%0,%1,%2,%3}, [%4];"
                 : "=r"(r[0]), "=r"(r[1]), "=r"(r[2]), "=r"(r[3]) : "r"(a));
}
__device__ __forceinline__ void ldsm4t(uint32_t* r, uint32_t a) {
    asm volatile("ldmatrix.sync.aligned.m8n8.x4.trans.shared.b16 {%0,%1,%2,%3}, [%4];"
                 : "=r"(r[0]), "=r"(r[1]), "=r"(r[2]), "=r"(r[3]) : "r"(a));
}
__device__ __forceinline__ void mma16816(float* c, const uint32_t* a, uint32_t b0, uint32_t b1) {
    asm volatile("mma.sync.aligned.m16n8k16.row.col.f32.bf16.bf16.f32 "
                 "{%0,%1,%2,%3}, {%4,%5,%6,%7}, {%8,%9}, {%0,%1,%2,%3};"
                 : "+f"(c[0]), "+f"(c[1]), "+f"(c[2]), "+f"(c[3])
                 : "r"(a[0]), "r"(a[1]), "r"(a[2]), "r"(a[3]), "r"(b0), "r"(b1));
}
__device__ __forceinline__ void cp16(uint32_t d, const void* s) {
    asm volatile("cp.async.cg.shared.global [%0], [%1], 16;" :: "r"(d), "l"(s));
}
__device__ __forceinline__ void cp16z(uint32_t d, const void* s, int sz) {
    asm volatile("cp.async.cg.shared.global [%0], [%1], 16, %2;" :: "r"(d), "l"(s), "r"(sz));
}
__device__ __forceinline__ void cp_commit() {
    asm volatile("cp.async.commit_group;" ::: "memory");
}
template<int N> __device__ __forceinline__ void cp_wait() {
    asm volatile("cp.async.wait_group %0;" :: "n"(N) : "memory");
}
__device__ __forceinline__ uint32_t sw128(uint32_t off) { return off ^ ((off >> 3) & 0x70); }

// pack two fp32 into bf16x2 hi + residual lo
__device__ __forceinline__ void packsplit(float x, float y, uint32_t& hi, uint32_t& lo) {
    uint32_t h; asm("cvt.rn.bf16x2.f32 %0, %1, %2;" : "=r"(h) : "f"(y), "f"(x));
    float hx = __uint_as_float(h << 16);
    float hy = __uint_as_float(h & 0xffff0000u);
    uint32_t l; asm("cvt.rn.bf16x2.f32 %0, %1, %2;" : "=r"(l) : "f"(y - hy), "f"(x - hx));
    hi = h; lo = l;
}

// ============================================================================
// split kernels: x (one tensor) and the 4 weights batched over blockIdx.y
// ============================================================================
__global__ void __launch_bounds__(256) split_kernel(
    const float* __restrict__ src, __nv_bfloat16* __restrict__ hi,
    __nv_bfloat16* __restrict__ lo, int n4)
{
    int i = blockIdx.x * 256 + threadIdx.x;
    if (i >= n4) return;
    float4 v = ((const float4*)src)[i];
    uint32_t h0, l0, h1, l1;
    packsplit(v.x, v.y, h0, l0);
    packsplit(v.z, v.w, h1, l1);
    ((uint2*)hi)[i] = make_uint2(h0, h1);
    ((uint2*)lo)[i] = make_uint2(l0, l1);
}

__global__ void __launch_bounds__(256) split_w_kernel(
    const float* __restrict__ w0, const float* __restrict__ w1,
    const float* __restrict__ w2, const float* __restrict__ w3,
    __nv_bfloat16* __restrict__ hi, __nv_bfloat16* __restrict__ lo)
{
    const int which = blockIdx.y;
    const float* src = (which == 0) ? w0 : (which == 1) ? w1 : (which == 2) ? w2 : w3;
    const int n4 = WSZ / 4;
    int i = blockIdx.x * 256 + threadIdx.x;
    if (i >= n4) return;
    float4 v = ((const float4*)src)[i];
    uint32_t h0, l0, h1, l1;
    packsplit(v.x, v.y, h0, l0);
    packsplit(v.z, v.w, h1, l1);
    size_t base = (size_t)which * (WSZ / 4);
    ((uint2*)hi)[base + i] = make_uint2(h0, h1);
    ((uint2*)lo)[base + i] = make_uint2(l0, l1);
}

// ============================================================================
// Split-bf16 GEMM (NT) via mma.sync.m16n8k16 — R12 config (best measured).
// Tile 128x128x64, 2 stages, K-chunk 64, separate hi/lo 16KB tiles.
// ============================================================================
#define T_AH 0
#define T_AL 16384
#define T_WH 32768
#define T_WL 49152
#define STAGE_B 65536
#define GEMM_SMEM (2*STAGE_B)

__device__ __forceinline__ void gemm_body(
    const __nv_bfloat16* __restrict__ Ah, const __nv_bfloat16* __restrict__ Al,
    const __nv_bfloat16* __restrict__ Wh, const __nv_bfloat16* __restrict__ Wl,
    const float* __restrict__ bias, float* __restrict__ C, int M,
    int m0, int n0, char* smem)
{
    const uint32_t sb = smem_u32(smem);
    const int tid  = threadIdx.x;
    const int lane = tid & 31;
    const int warp = tid >> 5;
    const int wm = (warp >> 2) * 64;
    const int wn = (warp & 3) * 32;
    const int lrow = tid >> 3;
    const int lch  = tid & 7;

    float acc[4][4][4];
#pragma unroll
    for (int mi = 0; mi < 4; ++mi)
#pragma unroll
        for (int ni = 0; ni < 4; ++ni)
#pragma unroll
            for (int j = 0; j < 4; ++j) acc[mi][ni][j] = 0.f;

    auto load_stage = [&](int c, int buf) {
        const uint32_t db = sb + buf * STAGE_B;
        const int kc = c * 64 + lch * 8;
#pragma unroll
        for (int i = 0; i < 4; ++i) {
            const int row = lrow + 32 * i;
            const uint32_t so = sw128((uint32_t)(row * 128 + lch * 16));
            const int mg = m0 + row;
            const int sz = (mg < M) ? 16 : 0;
            const size_t ao = (size_t)mg * DIM_ + kc;
            cp16z(db + T_AH + so, Ah + ao, sz);
            cp16z(db + T_AL + so, Al + ao, sz);
            const size_t wo = (size_t)(n0 + row) * DIM_ + kc;
            cp16(db + T_WH + so, Wh + wo);
            cp16(db + T_WL + so, Wl + wo);
        }
    };

    load_stage(0, 0);
    cp_commit();

    for (int c = 0; c < 24; ++c) {
        if (c < 23) { load_stage(c + 1, (c + 1) & 1); cp_commit(); }
        if (c < 23) cp_wait<1>(); else cp_wait<0>();
        __syncthreads();

        const uint32_t base = sb + (c & 1) * STAGE_B;
        const int rA = wm + (lane & 15);
        const int rW = wn + (lane & 15);
#pragma unroll
        for (int ks = 0; ks < 4; ++ks) {
            const int kb = ks * 32 + ((lane >> 4) << 4);
            uint32_t ah[4][4], al[4][4], wh[2][4], wl[2][4];
#pragma unroll
            for (int mi = 0; mi < 4; ++mi) {
                ldsm4(ah[mi], base + T_AH + sw128((uint32_t)((rA + mi * 16) * 128 + kb)));
                ldsm4(al[mi], base + T_AL + sw128((uint32_t)((rA + mi * 16) * 128 + kb)));
            }
#pragma unroll
            for (int nj = 0; nj < 2; ++nj) {
                ldsm4(wh[nj], base + T_WH + sw128((uint32_t)((rW + nj * 16) * 128 + kb)));
                ldsm4(wl[nj], base + T_WL + sw128((uint32_t)((rW + nj * 16) * 128 + kb)));
            }
#pragma unroll
            for (int mi = 0; mi < 4; ++mi)
#pragma unroll
                for (int ni = 0; ni < 4; ++ni) {
                    const int nj = ni >> 1, hf = ni & 1;
                    const uint32_t b0h = wh[nj][hf], b1h = wh[nj][hf + 2];
                    const uint32_t b0l = wl[nj][hf], b1l = wl[nj][hf + 2];
                    mma16816(acc[mi][ni], ah[mi], b0h, b1h);
                    mma16816(acc[mi][ni], al[mi], b0h, b1h);
                    mma16816(acc[mi][ni], ah[mi], b0l, b1l);
                }
        }
        __syncthreads();
    }

    float2 bv[4];
#pragma unroll
    for (int ni = 0; ni < 4; ++ni) {
        const int n = n0 + wn + ni * 8 + (lane & 3) * 2;
        bv[ni] = *(const float2*)&bias[n];
    }
#pragma unroll
    for (int mi = 0; mi < 4; ++mi) {
        const int m = m0 + wm + mi * 16 + (lane >> 2);
#pragma unroll
        for (int ni = 0; ni < 4; ++ni) {
            const int n = n0 + wn + ni * 8 + (lane & 3) * 2;
            if (m < M) {
                float2 o = make_float2(acc[mi][ni][0] + bv[ni].x, acc[mi][ni][1] + bv[ni].y);
                *(float2*)&C[(size_t)m * DIM_ + n] = o;
            }
            if (m + 8 < M) {
                float2 o = make_float2(acc[mi][ni][2] + bv[ni].x, acc[mi][ni][3] + bv[ni].y);
                *(float2*)&C[(size_t)(m + 8) * DIM_ + n] = o;
            }
        }
    }
}

// plain GEMM (output projection)
__global__ void __launch_bounds__(256) gemm_mma(
    const __nv_bfloat16* __restrict__ Ah, const __nv_bfloat16* __restrict__ Al,
    const __nv_bfloat16* __restrict__ Wh, const __nv_bfloat16* __restrict__ Wl,
    const float* __restrict__ bias, float* __restrict__ C, int M)
{
    extern __shared__ __align__(16) char smem[];
    gemm_body(Ah, Al, Wh, Wl, bias, C, M, blockIdx.y * 128, blockIdx.x * 128, smem);
}

// fused QKV GEMM: blockIdx.x in [0,36): which = bx/12, n0 = (bx%12)*128
__global__ void __launch_bounds__(256) gemm_qkv(
    const __nv_bfloat16* __restrict__ Ah, const __nv_bfloat16* __restrict__ Al,
    const __nv_bfloat16* __restrict__ Whb, const __nv_bfloat16* __restrict__ Wlb,
    const float* __restrict__ bq, const float* __restrict__ bk, const float* __restrict__ bv_,
    float* __restrict__ outbase, int M)
{
    extern __shared__ __align__(16) char smem[];
    const int which = blockIdx.x / 12;
    const int n0 = (blockIdx.x % 12) * 128;
    const __nv_bfloat16* Wh = Whb + (size_t)which * WSZ;
    const __nv_bfloat16* Wl = Wlb + (size_t)which * WSZ;
    const float* bias = (which == 0) ? bq : ((which == 1) ? bk : bv_);
    float* C = outbase + (size_t)which * SD;
    gemm_body(Ah, Al, Wh, Wl, bias, C, M, blockIdx.y * 128, n0, smem);
}

// ============================================================================
// Cache window copy -> split bf16 head-major K/V  (tokens [0, NEW0))
// ============================================================================
__global__ void cache_copy_kernel(const float* __restrict__ ck, const float* __restrict__ cv,
                                  __nv_bfloat16* __restrict__ Kh, __nv_bfloat16* __restrict__ Kl,
                                  __nv_bfloat16* __restrict__ Vh, __nv_bfloat16* __restrict__ Vl)
{
    int t = blockIdx.x;                 // 0..2511
    int e = threadIdx.x << 2;           // 384 threads * 4 = 1536
    int n = e >> 7, d = e & 127;
    size_t dst = ((size_t)n * KV + t) * HD + d;
    float4 kv = *(const float4*)&ck[(size_t)(WIN0 + t) * DIM_ + e];
    float4 vv = *(const float4*)&cv[(size_t)(WIN0 + t) * DIM_ + e];
    uint32_t h0, l0, h1, l1;
    packsplit(kv.x, kv.y, h0, l0); packsplit(kv.z, kv.w, h1, l1);
    *(uint2*)&Kh[dst] = make_uint2(h0, h1);
    *(uint2*)&Kl[dst] = make_uint2(l0, l1);
    packsplit(vv.x, vv.y, h0, l0); packsplit(vv.z, vv.w, h1, l1);
    *(uint2*)&Vh[dst] = make_uint2(h0, h1);
    *(uint2*)&Vl[dst] = make_uint2(l0, l1);
}

// ============================================================================
// RMSNorm(1536) + RoPE -> split-bf16 head-major Q, K(@NEW0), V(@NEW0)
// ============================================================================
__global__ void __launch_bounds__(256) norm_rope_kernel(
    const float* __restrict__ yq, const float* __restrict__ yk, const float* __restrict__ yv,
    const float* __restrict__ theta, const float* __restrict__ gq, const float* __restrict__ gk,
    __nv_bfloat16* __restrict__ Qh, __nv_bfloat16* __restrict__ Ql,
    __nv_bfloat16* __restrict__ Kh, __nv_bfloat16* __restrict__ Kl,
    __nv_bfloat16* __restrict__ Vh, __nv_bfloat16* __restrict__ Vl)
{
    const int s = blockIdx.x;
    const int tid = threadIdx.x;
    __shared__ float cs[64], sn[64];
    __shared__ float redq[8], redk[8];

    const int f   = s / 1560;           // frame_seqlen = 30*52
    const int rem = s % 1560;
    const int h   = rem / 52;
    const int w   = rem % 52;

    if (tid < 64) {
        int j = tid;
        int row = (j < 22) ? (5 + f) : ((j < 43) ? h : w);
        float ang = theta[row * 64 + j];
        float sv, cv; sincosf(ang, &sv, &cv);
        cs[j] = cv; sn[j] = sv;
    }

    const float* q = yq + (size_t)s * DIM_;
    const float* k = yk + (size_t)s * DIM_;
    const float* v = yv + (size_t)s * DIM_;

    float sq = 0.f, sk = 0.f;
    for (int e = tid; e < DIM_; e += 256) {
        float a = q[e]; sq += a * a;
        float b = k[e]; sk += b * b;
    }
#pragma unroll
    for (int off = 16; off; off >>= 1) {
        sq += __shfl_xor_sync(0xffffffffu, sq, off);
        sk += __shfl_xor_sync(0xffffffffu, sk, off);
    }
    if ((tid & 31) == 0) { redq[tid >> 5] = sq; redk[tid >> 5] = sk; }
    __syncthreads();
    float tq = 0.f, tk = 0.f;
#pragma unroll
    for (int i = 0; i < 8; ++i) { tq += redq[i]; tk += redk[i]; }
    const float rq = rsqrtf(tq * (1.f / 1536.f) + 1e-6f);
    const float rk = rsqrtf(tk * (1.f / 1536.f) + 1e-6f);

    for (int p = tid; p < 768; p += 256) {
        int n = p >> 6, j = p & 63;
        float c = cs[j], si = sn[j];
        int e = p << 1;
        float xr = q[e]     * rq * gq[e];
        float xi = q[e + 1] * rq * gq[e + 1];
        float qr = (xr * c - xi * si) * QSCALE;
        float qi = (xr * si + xi * c) * QSCALE;
        size_t qo = ((size_t)n * S_TOK + s) * HD + (j << 1);
        uint32_t hi, lo;
        packsplit(qr, qi, hi, lo);
        *(uint32_t*)&Qh[qo] = hi; *(uint32_t*)&Ql[qo] = lo;
        float kr0 = k[e]     * rk * gk[e];
        float ki0 = k[e + 1] * rk * gk[e + 1];
        float kr = kr0 * c - ki0 * si;
        float ki = kr0 * si + ki0 * c;
        size_t ko = ((size_t)n * KV + NEW0 + s) * HD + (j << 1);
        packsplit(kr, ki, hi, lo);
        *(uint32_t*)&Kh[ko] = hi; *(uint32_t*)&Kl[ko] = lo;
        float v0 = v[e], v1 = v[e + 1];
        packsplit(v0, v1, hi, lo);
        *(uint32_t*)&Vh[ko] = hi; *(uint32_t*)&Vl[ko] = lo;
    }
}

// ============================================================================
// Flash attention via mma.sync split-bf16 (full KV). 128q x head, 256 thr.
// Epilogue writes split-bf16 token-major directly.
// ============================================================================
#define AT_SMEM (2*65536)

__global__ void __launch_bounds__(256, 1) attn_mma(
    const __nv_bfloat16* __restrict__ Qh_, const __nv_bfloat16* __restrict__ Ql_,
    const __nv_bfloat16* __restrict__ Kh_, const __nv_bfloat16* __restrict__ Kl_,
    const __nv_bfloat16* __restrict__ Vh_, const __nv_bfloat16* __restrict__ Vl_,
    __nv_bfloat16* __restrict__ Ohi, __nv_bfloat16* __restrict__ Olo)
{
    extern __shared__ __align__(16) char smem[];
    const uint32_t sb = smem_u32(smem);
    const int tid = threadIdx.x, lane = tid & 31, warp = tid >> 5;
    const int head = blockIdx.y;
    const int q0 = blockIdx.x * 128;

    // ---- stage Q tile (hi at 0, lo at +32768), then load A-fragments ----
#pragma unroll
    for (int i = 0; i < 8; ++i) {
        int slot = tid + i * 256;
        int row = slot >> 4, ch = slot & 15;
        int qg = q0 + row;
        int sz = (qg < S_TOK) ? 16 : 0;
        if (qg >= S_TOK) qg = S_TOK - 1;
        const size_t off = ((size_t)head * S_TOK + qg) * HD + ch * 8;
        uint32_t d = sb + (row << 8) + (((uint32_t)(ch ^ (row & 7))) << 4);
        cp16z(d, Qh_ + off, sz);
        cp16z(d + 32768, Ql_ + off, sz);
    }
    cp_commit(); cp_wait<0>(); __syncthreads();

    uint32_t qh[8][4], ql[8][4];
    {
        const int row = warp * 16 + (lane & 15);
#pragma unroll
        for (int kc = 0; kc < 8; ++kc) {
            int ch = 2 * kc + ((lane >> 4) & 1);
            uint32_t a = sb + (row << 8) + (((uint32_t)(ch ^ (row & 7))) << 4);
            ldsm4(qh[kc], a);
            ldsm4(ql[kc], a + 32768);
        }
    }
    __syncthreads();

    float oacc[16][4];
#pragma unroll
    for (int i = 0; i < 16; ++i)
#pragma unroll
        for (int j = 0; j < 4; ++j) oacc[i][j] = 0.f;
    float mr0 = -1e30f, mr1 = -1e30f, lr0 = 0.f, lr1 = 0.f;

    auto load_kv = [&](int kt, int buf) {
        const uint32_t db = sb + buf * 65536;
        const int t0 = kt * 64;
#pragma unroll
        for (int i = 0; i < 4; ++i) {
            int slot = tid + i * 256;
            int row = slot >> 4, ch = slot & 15;
            const size_t off = ((size_t)head * KV + t0 + row) * HD + ch * 8;
            uint32_t d = (uint32_t)((row << 8) + ((ch ^ (row & 7)) << 4));
            cp16(db + d,         Kh_ + off);
            cp16(db + 16384 + d, Kl_ + off);
            cp16(db + 32768 + d, Vh_ + off);
            cp16(db + 49152 + d, Vl_ + off);
        }
    };

    load_kv(0, 0); cp_commit();

    for (int kt = 0; kt < NKT; ++kt) {
        if (kt < NKT - 1) { load_kv(kt + 1, (kt + 1) & 1); cp_commit(); cp_wait<1>(); }
        else cp_wait<0>();
        __syncthreads();
        const uint32_t kb = sb + (kt & 1) * 65536;

        // ---- S = Q K^T ----
        float sacc[8][4];
#pragma unroll
        for (int i = 0; i < 8; ++i)
#pragma unroll
            for (int j = 0; j < 4; ++j) sacc[i][j] = 0.f;

#pragma unroll
        for (int kc = 0; kc < 8; ++kc) {
#pragma unroll
            for (int ng = 0; ng < 4; ++ng) {
                const int key = 16 * ng + (lane & 15);
                const int ch = 2 * kc + ((lane >> 4) & 1);
                uint32_t a = kb + (key << 8) + (((uint32_t)(ch ^ (key & 7))) << 4);
                uint32_t khf[4], klf[4];
                ldsm4(khf, a);
                ldsm4(klf, a + 16384);
                mma16816(sacc[2 * ng],     qh[kc], khf[0], khf[2]);
                mma16816(sacc[2 * ng],     ql[kc], khf[0], khf[2]);
                mma16816(sacc[2 * ng],     qh[kc], klf[0], klf[2]);
                mma16816(sacc[2 * ng + 1], qh[kc], khf[1], khf[3]);
                mma16816(sacc[2 * ng + 1], ql[kc], khf[1], khf[3]);
                mma16816(sacc[2 * ng + 1], qh[kc], klf[1], klf[3]);
            }
        }

        // ---- online softmax in fragments ----
        float tm0 = -1e30f, tm1 = -1e30f;
#pragma unroll
        for (int i = 0; i < 8; ++i) {
            tm0 = fmaxf(tm0, fmaxf(sacc[i][0], sacc[i][1]));
            tm1 = fmaxf(tm1, fmaxf(sacc[i][2], sacc[i][3]));
        }
        tm0 = fmaxf(tm0, __shfl_xor_sync(0xffffffffu, tm0, 1));
        tm0 = fmaxf(tm0, __shfl_xor_sync(0xffffffffu, tm0, 2));
        tm1 = fmaxf(tm1, __shfl_xor_sync(0xffffffffu, tm1, 1));
        tm1 = fmaxf(tm1, __shfl_xor_sync(0xffffffffu, tm1, 2));
        const float mn0 = fmaxf(mr0, tm0), mn1 = fmaxf(mr1, tm1);
        const float al0 = __expf(mr0 - mn0), al1 = __expf(mr1 - mn1);
        mr0 = mn0; mr1 = mn1;

        float rs0 = 0.f, rs1 = 0.f;
#pragma unroll
        for (int i = 0; i < 8; ++i) {
            sacc[i][0] = __expf(sacc[i][0] - mn0); rs0 += sacc[i][0];
            sacc[i][1] = __expf(sacc[i][1] - mn0); rs0 += sacc[i][1];
            sacc[i][2] = __expf(sacc[i][2] - mn1); rs1 += sacc[i][2];
            sacc[i][3] = __expf(sacc[i][3] - mn1); rs1 += sacc[i][3];
        }
        rs0 += __shfl_xor_sync(0xffffffffu, rs0, 1);
        rs0 += __shfl_xor_sync(0xffffffffu, rs0, 2);
        rs1 += __shfl_xor_sync(0xffffffffu, rs1, 1);
        rs1 += __shfl_xor_sync(0xffffffffu, rs1, 2);
        lr0 = lr0 * al0 + rs0;
        lr1 = lr1 * al1 + rs1;

#pragma unroll
        for (int i = 0; i < 16; ++i) {
            oacc[i][0] *= al0; oacc[i][1] *= al0;
            oacc[i][2] *= al1; oacc[i][3] *= al1;
        }

        // ---- pack P into split-bf16 A-fragments ----
        uint32_t ph[4][4], pl[4][4];
#pragma unroll
        for (int kc = 0; kc < 4; ++kc) {
            packsplit(sacc[2 * kc][0],     sacc[2 * kc][1],     ph[kc][0], pl[kc][0]);
            packsplit(sacc[2 * kc][2],     sacc[2 * kc][3],     ph[kc][1], pl[kc][1]);
            packsplit(sacc[2 * kc + 1][0], sacc[2 * kc + 1][1], ph[kc][2], pl[kc][2]);
            packsplit(sacc[2 * kc + 1][2], sacc[2 * kc + 1][3], ph[kc][3], pl[kc][3]);
        }

        // ---- O += P V ----
#pragma unroll
        for (int kc = 0; kc < 4; ++kc) {
#pragma unroll
            for (int ng = 0; ng < 8; ++ng) {
                const int key = 16 * kc + (lane & 15);
                const int ch = 2 * ng + ((lane >> 4) & 1);
                uint32_t a = kb + 32768 + (key << 8) + (((uint32_t)(ch ^ (key & 7))) << 4);
                uint32_t vhf[4], vlf[4];
                ldsm4t(vhf, a);
                ldsm4t(vlf, a + 16384);
                mma16816(oacc[2 * ng],     ph[kc], vhf[0], vhf[1]);
                mma16816(oacc[2 * ng],     pl[kc], vhf[0], vhf[1]);
                mma16816(oacc[2 * ng],     ph[kc], vlf[0], vlf[1]);
                mma16816(oacc[2 * ng + 1], ph[kc], vhf[2], vhf[3]);
                mma16816(oacc[2 * ng + 1], pl[kc], vhf[2], vhf[3]);
                mma16816(oacc[2 * ng + 1], ph[kc], vlf[2], vlf[3]);
            }
        }
        __syncthreads();
    }

    // ---- epilogue: normalize and write split-bf16 token-major ----
    const float inv0 = 1.f / lr0, inv1 = 1.f / lr1;
    const int r0 = warp * 16 + (lane >> 2);
    const int cn = (lane & 3) * 2;
    const int qa = q0 + r0, qb = qa + 8;
#pragma unroll
    for (int ni = 0; ni < 16; ++ni) {
        const int col = head * HD + ni * 8 + cn;
        uint32_t hi, lo;
        if (qa < S_TOK) {
            packsplit(oacc[ni][0] * inv0, oacc[ni][1] * inv0, hi, lo);
            size_t off = (size_t)qa * DIM_ + col;
            *(uint32_t*)&Ohi[off] = hi; *(uint32_t*)&Olo[off] = lo;
        }
        if (qb < S_TOK) {
            packsplit(oacc[ni][2] * inv1, oacc[ni][3] * inv1, hi, lo);
            size_t off = (size_t)qb * DIM_ + col;
            *(uint32_t*)&Ohi[off] = hi; *(uint32_t*)&Olo[off] = lo;
        }
    }
}

// ============================================================================
extern "C" void kernel_launch(void* const* d_in, const int* in_sizes, int n_in,
                              void* d_out, int out_size)
{
    const float* x     = (const float*)d_in[0];
    const float* theta = (const float*)d_in[1];
    const float* ck    = (const float*)d_in[2];
    const float* cv    = (const float*)d_in[3];
    const float* wq    = (const float*)d_in[4];
    const float* bq    = (const float*)d_in[5];
    const float* wk    = (const float*)d_in[6];
    const float* bk    = (const float*)d_in[7];
    const float* wv    = (const float*)d_in[8];
    const float* bv    = (const float*)d_in[9];
    const float* wo    = (const float*)d_in[10];
    const float* bo    = (const float*)d_in[11];
    const float* gq    = (const float*)d_in[12];
    const float* gk    = (const float*)d_in[13];
    float* out = (float*)d_out;

    float* scr = nullptr;
    cudaGetSymbolAddress((void**)&scr, g_scratch);
    float* yq  = scr;
    float* yk  = scr + (size_t)SD;
    float* yv  = scr + 2 * (size_t)SD;

    __nv_bfloat16 *xhi, *xlo, *whi, *wlo, *ohi, *olo;
    __nv_bfloat16 *Qh, *Ql, *Kh, *Kl, *Vh, *Vl;
    cudaGetSymbolAddress((void**)&xhi, g_xhi);
    cudaGetSymbolAddress((void**)&xlo, g_xlo);
    cudaGetSymbolAddress((void**)&whi, g_whi);
    cudaGetSymbolAddress((void**)&wlo, g_wlo);
    cudaGetSymbolAddress((void**)&ohi, g_ohi);
    cudaGetSymbolAddress((void**)&olo, g_olo);
    cudaGetSymbolAddress((void**)&Qh, g_qh);
    cudaGetSymbolAddress((void**)&Ql, g_ql);
    cudaGetSymbolAddress((void**)&Kh, g_kh);
    cudaGetSymbolAddress((void**)&Kl, g_kl);
    cudaGetSymbolAddress((void**)&Vh, g_vh);
    cudaGetSymbolAddress((void**)&Vl, g_vl);

    cudaFuncSetAttribute(gemm_mma, cudaFuncAttributeMaxDynamicSharedMemorySize, GEMM_SMEM);
    cudaFuncSetAttribute(gemm_qkv, cudaFuncAttributeMaxDynamicSharedMemorySize, GEMM_SMEM);
    cudaFuncSetAttribute(attn_mma, cudaFuncAttributeMaxDynamicSharedMemorySize, AT_SMEM);

    const int SD4 = SD / 4, W4 = WSZ / 4;
    // launch 0: split x ; launch 1: split all 4 weights
    split_kernel<<<(SD4 + 255) / 256, 256>>>(x, xhi, xlo, SD4);
    split_w_kernel<<<dim3((W4 + 255) / 256, 4), 256>>>(wq, wk, wv, wo, whi, wlo);

    // launch 2: fused QKV projection (grid 36x25)
    gemm_qkv<<<dim3(36, 25), 256, GEMM_SMEM>>>(xhi, xlo, whi, wlo, bq, bk, bv, scr, S_TOK);

    // launches 3, 4
    cache_copy_kernel<<<NEW0, 384>>>(ck, cv, Kh, Kl, Vh, Vl);
    norm_rope_kernel<<<S_TOK, 256>>>(yq, yk, yv, theta, gq, gk, Qh, Ql, Kh, Kl, Vh, Vl);

    // launch 5: attention (profiled by ncu -s 5 -c 1)
    attn_mma<<<dim3(25, NH), 256, AT_SMEM>>>(Qh, Ql, Kh, Kl, Vh, Vl, ohi, olo);

    // launch 6: output projection
    gemm_mma<<<dim3(12, 25), 256, GEMM_SMEM>>>(ohi, olo, whi + 3 * (size_t)WSZ, wlo + 3 * (size_t)WSZ, bo, out, S_TOK);
}